// round 5
// baseline (speedup 1.0000x reference)
#include <cuda_runtime.h>

// Fixed problem shape
#define BATCH 8
#define CDIM  64
#define NPTS  4096
#define KNN   20
#define TM    128   // targets per block == threads per block
#define TC    32    // candidate tile size (keeps static SMEM < 48KB)
#define CAP   16    // per-thread candidate buffer slots

// ---------------------------------------------------------------------------
// One thread = one target point.
//  - Target features in registers; candidate tile (32 pts x 64 ch,
//    channel-major) in SMEM; dots via uniform float4 broadcast LDS.
//  - Top-K via threshold + deferred merge: hot path only appends passing
//    candidates (packed u64 key = d2_bits<<32 | idx, exact lax.top_k order)
//    to a per-thread SMEM buffer; rare warp-wide merges insertion-sort the
//    buffer into a per-thread SMEM-resident sorted top-20 and refresh the
//    threshold. Stale-threshold false passes are filtered at merge.
//  - d2 = fma(dot, -2, sq_t + sq_j), sequential-c accumulation: bit-identical
//    to the passing round-3/4 kernels (rel_err 9.3e-4).
//  - Output dtype float32: indices written as floats (exact).
// ---------------------------------------------------------------------------
__global__ void __launch_bounds__(TM) knn_all(const float* __restrict__ x,
                                              float* __restrict__ out) {
    __shared__ __align__(16) float sf[CDIM * TC];           // 8 KB tile
    __shared__ __align__(16) float s_csq[TC];               // candidate |.|^2
    __shared__ unsigned long long s_top[KNN][TM];           // 20 KB sorted topK
    __shared__ unsigned long long s_buf[CAP][TM];           // 16 KB buffers

    const int b   = blockIdx.y;
    const int tid = threadIdx.x;
    const int tgt = blockIdx.x * TM + tid;
    const float* xb = x + b * CDIM * NPTS;

    // Target features -> registers; target squared norm.
    float tq[CDIM];
    float sqt = 0.f;
#pragma unroll
    for (int c = 0; c < CDIM; c++) {
        tq[c] = xb[c * NPTS + tgt];
        sqt = fmaf(tq[c], tq[c], sqt);
    }

    // Sorted top-K column in SMEM (ascending u64 keys), sentinel = max.
#pragma unroll
    for (int k = 0; k < KNN; k++) s_top[k][tid] = ~0ull;
    unsigned long long thresh = ~0ull;   // current 20th-best key (stale ok)
    int cnt = 0;                         // buffered candidates

    const int cand = tid & (TC - 1);     // candidate column this thread stages
    const int cgrp = tid >> 5;           // channel group 0..3 (TM = 4*TC)

    for (int j0 = 0; j0 < NPTS; j0 += TC) {
        __syncthreads();                 // prior tile fully consumed
#pragma unroll
        for (int c = cgrp; c < CDIM; c += 4)
            sf[c * TC + cand] = xb[c * NPTS + j0 + cand];
        __syncthreads();
        if (tid < TC) {                  // candidate norms from staged tile
            float s = 0.f;
#pragma unroll
            for (int c = 0; c < CDIM; c++) {
                float v = sf[c * TC + tid];
                s = fmaf(v, v, s);
            }
            s_csq[tid] = s;
        }
        __syncthreads();

        for (int jg = 0; jg < TC; jg += 4) {
            float acc[4] = {0.f, 0.f, 0.f, 0.f};
            const float4* row4 = reinterpret_cast<const float4*>(sf) + (jg >> 2);
#pragma unroll
            for (int c = 0; c < CDIM; c++) {
                float4 cv = row4[c * (TC / 4)];   // uniform broadcast LDS.128
                float a = tq[c];
                acc[0] = fmaf(a, cv.x, acc[0]);
                acc[1] = fmaf(a, cv.y, acc[1]);
                acc[2] = fmaf(a, cv.z, acc[2]);
                acc[3] = fmaf(a, cv.w, acc[3]);
            }
            float4 cs = *reinterpret_cast<const float4*>(s_csq + jg);
#pragma unroll
            for (int u = 0; u < 4; u++) {
                float csu = (u == 0) ? cs.x : (u == 1) ? cs.y
                          : (u == 2) ? cs.z : cs.w;
                int   j   = j0 + jg + u;
                float t   = sqt + csu;
                float d   = fmaf(acc[u], -2.0f, t);   // one final rounding
                unsigned long long key =
                    ((unsigned long long)__float_as_uint(d) << 32) |
                    (unsigned int)j;
                if (j != tgt && key < thresh) {       // cheap append path
                    s_buf[cnt][tid] = key;
                    cnt++;
                }
            }
            // Rare warp-wide merge; margin 4 so next group can't overflow.
            if (__any_sync(0xffffffffu, cnt > CAP - 4)) {
                for (int i = 0; i < cnt; i++) {
                    unsigned long long kv = s_buf[i][tid];
                    if (kv < s_top[KNN - 1][tid]) {
                        int k = KNN - 1;
                        while (k > 0 && s_top[k - 1][tid] > kv) {
                            s_top[k][tid] = s_top[k - 1][tid];
                            k--;
                        }
                        s_top[k][tid] = kv;
                    }
                }
                cnt = 0;
                thresh = s_top[KNN - 1][tid];
            }
        }
    }

    // Final merge of any leftovers.
    for (int i = 0; i < cnt; i++) {
        unsigned long long kv = s_buf[i][tid];
        if (kv < s_top[KNN - 1][tid]) {
            int k = KNN - 1;
            while (k > 0 && s_top[k - 1][tid] > kv) {
                s_top[k][tid] = s_top[k - 1][tid];
                k--;
            }
            s_top[k][tid] = kv;
        }
    }

    // Emit ascending (distance, index); output dtype is float32.
    const int base0 = ((0 * BATCH + b) * NPTS + tgt) * KNN;
    const int base1 = ((1 * BATCH + b) * NPTS + tgt) * KNN;
    const float ftgt = (float)tgt;
#pragma unroll
    for (int p = 0; p < KNN; p++) {
        out[base0 + p] = (float)(int)(unsigned int)(s_top[p][tid] & 0xffffffffu);
        out[base1 + p] = ftgt;
    }
}

// ---------------------------------------------------------------------------
extern "C" void kernel_launch(void* const* d_in, const int* in_sizes, int n_in,
                              void* d_out, int out_size) {
    (void)in_sizes; (void)n_in; (void)out_size;
    const float* x = (const float*)d_in[0];
    float* out = (float*)d_out;

    dim3 grid(NPTS / TM, BATCH);
    knn_all<<<grid, TM>>>(x, out);
}

// round 6
// speedup vs baseline: 1.3683x; 1.3683x over previous
#include <cuda_runtime.h>

// Fixed problem shape
#define BATCH 8
#define CDIM  64
#define NPTS  4096
#define KNN   20
#define TM    128    // targets per block == threads per block
#define TC    32     // candidate tile size
#define CAP   16     // per-thread candidate buffer slots
#define NSPLIT 2
#define HALF_N (NPTS / NSPLIT)

// Scratch for split-K partial results: [half][k][b*NPTS+n], coalesced in n.
__device__ unsigned long long g_part[NSPLIT][KNN][BATCH * NPTS];

// ---------------------------------------------------------------------------
// Kernel 1: each CTA = 128 targets x one candidate half (2048 candidates).
// Distance arithmetic is bit-identical to the passing rounds 3-5:
//   dot: sequential ascending-c FFMA; csq: sequential ascending-c FFMA from
//   the staged tile; d2 = fma(dot, -2, sqt + csq).
// Top-K: threshold + deferred merge on packed u64 keys (d2_bits<<32 | idx);
// u64 '<' == lax.top_k (distance asc, lower index first) exactly.
// ---------------------------------------------------------------------------
__global__ void __launch_bounds__(TM) knn_half(const float* __restrict__ x) {
    __shared__ __align__(16) float sf[CDIM * TC];           // 8 KB tile
    __shared__ __align__(16) float s_csq[TC];
    __shared__ unsigned long long s_top[KNN][TM];           // 20 KB sorted topK
    __shared__ unsigned long long s_buf[CAP][TM];           // 16 KB buffers

    const int b    = blockIdx.y;
    const int half = blockIdx.z;
    const int tid  = threadIdx.x;
    const int tgt  = blockIdx.x * TM + tid;
    const float* xb = x + b * CDIM * NPTS;

    // Target features -> registers; target squared norm (ascending c).
    float tq[CDIM];
    float sqt = 0.f;
#pragma unroll
    for (int c = 0; c < CDIM; c++) {
        tq[c] = xb[c * NPTS + tgt];
        sqt = fmaf(tq[c], tq[c], sqt);
    }

#pragma unroll
    for (int k = 0; k < KNN; k++) s_top[k][tid] = ~0ull;
    unsigned long long thresh = ~0ull;
    int cnt = 0;

    const int cand = tid & (TC - 1);
    const int cgrp = tid >> 5;          // 0..3 (TM = 4*TC)
    const int jbeg = half * HALF_N;

    for (int jt = 0; jt < HALF_N; jt += TC) {
        const int j0 = jbeg + jt;
        __syncthreads();
#pragma unroll
        for (int c = cgrp; c < CDIM; c += 4)
            sf[c * TC + cand] = xb[c * NPTS + j0 + cand];
        __syncthreads();
        if (tid < TC) {                 // csq: ascending c, unchanged order
            float s = 0.f;
#pragma unroll
            for (int c = 0; c < CDIM; c++) {
                float v = sf[c * TC + tid];
                s = fmaf(v, v, s);
            }
            s_csq[tid] = s;
        }
        __syncthreads();

        for (int jg = 0; jg < TC; jg += 4) {
            float acc[4] = {0.f, 0.f, 0.f, 0.f};
            const float4* row4 = reinterpret_cast<const float4*>(sf) + (jg >> 2);
#pragma unroll
            for (int c = 0; c < CDIM; c++) {
                float4 cv = row4[c * (TC / 4)];   // uniform broadcast LDS.128
                float a = tq[c];
                acc[0] = fmaf(a, cv.x, acc[0]);
                acc[1] = fmaf(a, cv.y, acc[1]);
                acc[2] = fmaf(a, cv.z, acc[2]);
                acc[3] = fmaf(a, cv.w, acc[3]);
            }
            float4 cs = *reinterpret_cast<const float4*>(s_csq + jg);
#pragma unroll
            for (int u = 0; u < 4; u++) {
                float csu = (u == 0) ? cs.x : (u == 1) ? cs.y
                          : (u == 2) ? cs.z : cs.w;
                int   j   = j0 + jg + u;
                float t   = sqt + csu;
                float d   = fmaf(acc[u], -2.0f, t);   // one final rounding
                unsigned long long key =
                    ((unsigned long long)__float_as_uint(d) << 32) |
                    (unsigned int)j;
                if (j != tgt && key < thresh) {
                    s_buf[cnt][tid] = key;
                    cnt++;
                }
            }
            if (__any_sync(0xffffffffu, cnt > CAP - 4)) {
                for (int i = 0; i < cnt; i++) {
                    unsigned long long kv = s_buf[i][tid];
                    if (kv < s_top[KNN - 1][tid]) {
                        int k = KNN - 1;
                        while (k > 0 && s_top[k - 1][tid] > kv) {
                            s_top[k][tid] = s_top[k - 1][tid];
                            k--;
                        }
                        s_top[k][tid] = kv;
                    }
                }
                cnt = 0;
                thresh = s_top[KNN - 1][tid];
            }
        }
    }

    for (int i = 0; i < cnt; i++) {          // leftovers
        unsigned long long kv = s_buf[i][tid];
        if (kv < s_top[KNN - 1][tid]) {
            int k = KNN - 1;
            while (k > 0 && s_top[k - 1][tid] > kv) {
                s_top[k][tid] = s_top[k - 1][tid];
                k--;
            }
            s_top[k][tid] = kv;
        }
    }

    // Write sorted partial top-20 (coalesced in target index).
    const int col = b * NPTS + tgt;
#pragma unroll
    for (int p = 0; p < KNN; p++)
        g_part[half][p][col] = s_top[p][tid];
}

// ---------------------------------------------------------------------------
// Kernel 2: exact 2-pointer merge of the two sorted per-half top-20 lists.
// ---------------------------------------------------------------------------
__global__ void __launch_bounds__(128) knn_merge(float* __restrict__ out) {
    __shared__ unsigned long long sa[KNN][128];
    __shared__ unsigned long long sb[KNN][128];
    const int t   = threadIdx.x;
    const int idx = blockIdx.x * 128 + t;      // 0 .. B*N-1
#pragma unroll
    for (int p = 0; p < KNN; p++) {
        sa[p][t] = g_part[0][p][idx];          // coalesced
        sb[p][t] = g_part[1][p][idx];
    }
    const int b = idx >> 12;                   // NPTS = 4096
    const int n = idx & (NPTS - 1);
    const int base0 = ((0 * BATCH + b) * NPTS + n) * KNN;
    const int base1 = ((1 * BATCH + b) * NPTS + n) * KNN;
    const float ftgt = (float)n;

    int ia = 0, ib = 0;
#pragma unroll
    for (int p = 0; p < KNN; p++) {
        unsigned long long va = sa[ia][t];
        unsigned long long vb = sb[ib][t];
        bool ta = va < vb;                     // u64 order == exact key order
        unsigned long long v = ta ? va : vb;
        ia += ta ? 1 : 0;
        ib += ta ? 0 : 1;
        out[base0 + p] = (float)(int)(unsigned int)(v & 0xffffffffu);
        out[base1 + p] = ftgt;
    }
}

// ---------------------------------------------------------------------------
extern "C" void kernel_launch(void* const* d_in, const int* in_sizes, int n_in,
                              void* d_out, int out_size) {
    (void)in_sizes; (void)n_in; (void)out_size;
    const float* x = (const float*)d_in[0];
    float* out = (float*)d_out;

    dim3 grid(NPTS / TM, BATCH, NSPLIT);       // 32 x 8 x 2 = 512 CTAs
    knn_half<<<grid, TM>>>(x);
    knn_merge<<<(BATCH * NPTS) / 128, 128>>>(out);
}